// round 2
// baseline (speedup 1.0000x reference)
#include <cuda_runtime.h>
#include <math.h>

#define NN  50000
#define NE  800000
#define H   96
#define IND 256

// Scratch (__device__ globals per allocation rules)
__device__ float g_h[(size_t)NN * H];
__device__ float g_p[(size_t)NN * H];
__device__ float g_q[(size_t)NN * H];
__device__ float g_y[(size_t)NN * 2];   // pre-softmax logits accumulator

__device__ __forceinline__ float tanh_fast(float x) {
    float r;
    asm("tanh.approx.f32 %0, %1;" : "=f"(r) : "f"(x));
    return r;
}

// ---------------------------------------------------------------------------
__global__ void zero_y_kernel(float* __restrict__ y) {
    int i = blockIdx.x * blockDim.x + threadIdx.x;
    if (i < NN * 2) y[i] = 0.f;
}

// ---------------------------------------------------------------------------
// h = x @ W_in^T + b_in.  BM=64, BN=96, BK=16, 256 threads.
// ---------------------------------------------------------------------------
__global__ void gemm96(const float* __restrict__ A,
                       const float* __restrict__ W,
                       const float* __restrict__ bias,
                       float* __restrict__ C,
                       int M, int K)
{
    __shared__ float As[16][68];
    __shared__ float Bs[16][96];

    const int tid = threadIdx.x;
    const int tx  = tid & 31;
    const int ty  = tid >> 5;
    const int m0  = blockIdx.x * 64;

    float acc[8][3];
#pragma unroll
    for (int i = 0; i < 8; ++i)
#pragma unroll
        for (int j = 0; j < 3; ++j) acc[i][j] = 0.f;

    for (int k0 = 0; k0 < K; k0 += 16) {
        {
            int row  = tid >> 2;
            int kseg = (tid & 3) << 2;
            float4 v = make_float4(0.f, 0.f, 0.f, 0.f);
            int gm = m0 + row;
            if (gm < M)
                v = *(const float4*)(A + (size_t)gm * K + k0 + kseg);
            As[kseg + 0][row] = v.x;
            As[kseg + 1][row] = v.y;
            As[kseg + 2][row] = v.z;
            As[kseg + 3][row] = v.w;
        }
        for (int i = tid; i < 96 * 16; i += 256) {
            int n = i >> 4, k = i & 15;
            Bs[k][n] = W[(size_t)n * K + k0 + k];
        }
        __syncthreads();

#pragma unroll
        for (int k = 0; k < 16; ++k) {
            float b0 = Bs[k][tx], b1 = Bs[k][tx + 32], b2 = Bs[k][tx + 64];
#pragma unroll
            for (int i = 0; i < 8; ++i) {
                float a = As[k][ty * 8 + i];
                acc[i][0] += a * b0;
                acc[i][1] += a * b1;
                acc[i][2] += a * b2;
            }
        }
        __syncthreads();
    }

    float bb0 = bias[tx], bb1 = bias[tx + 32], bb2 = bias[tx + 64];

#pragma unroll
    for (int i = 0; i < 8; ++i) {
        int m = m0 + ty * 8 + i;
        if (m < M) {
            float* cr = C + (size_t)m * 96;
            cr[tx]      = acc[i][0] + bb0;
            cr[tx + 32] = acc[i][1] + bb1;
            cr[tx + 64] = acc[i][2] + bb2;
        }
    }
}

// ---------------------------------------------------------------------------
// Fused: p = h @ Wg[:, :96]^T,  q = h @ Wg[:, 96:]^T.  Shares the A tile.
// ---------------------------------------------------------------------------
__global__ void gemm_pq(const float* __restrict__ hmat,
                        const float* __restrict__ Wg,
                        float* __restrict__ p,
                        float* __restrict__ q)
{
    __shared__ float As[16][68];
    __shared__ float Bp[16][96];
    __shared__ float Bq[16][96];

    const int tid = threadIdx.x;
    const int tx  = tid & 31;
    const int ty  = tid >> 5;
    const int m0  = blockIdx.x * 64;

    float ap[8][3], aq[8][3];
#pragma unroll
    for (int i = 0; i < 8; ++i)
#pragma unroll
        for (int j = 0; j < 3; ++j) { ap[i][j] = 0.f; aq[i][j] = 0.f; }

    for (int k0 = 0; k0 < H; k0 += 16) {
        {
            int row  = tid >> 2;
            int kseg = (tid & 3) << 2;
            float4 v = make_float4(0.f, 0.f, 0.f, 0.f);
            int gm = m0 + row;
            if (gm < NN)
                v = *(const float4*)(hmat + (size_t)gm * H + k0 + kseg);
            As[kseg + 0][row] = v.x;
            As[kseg + 1][row] = v.y;
            As[kseg + 2][row] = v.z;
            As[kseg + 3][row] = v.w;
        }
        for (int i = tid; i < 96 * 16; i += 256) {
            int n = i >> 4, k = i & 15;
            Bp[k][n] = Wg[(size_t)n * (2 * H) + k0 + k];
            Bq[k][n] = Wg[(size_t)n * (2 * H) + H + k0 + k];
        }
        __syncthreads();

#pragma unroll
        for (int k = 0; k < 16; ++k) {
            float p0 = Bp[k][tx], p1 = Bp[k][tx + 32], p2 = Bp[k][tx + 64];
            float q0 = Bq[k][tx], q1 = Bq[k][tx + 32], q2 = Bq[k][tx + 64];
#pragma unroll
            for (int i = 0; i < 8; ++i) {
                float a = As[k][ty * 8 + i];
                ap[i][0] += a * p0; ap[i][1] += a * p1; ap[i][2] += a * p2;
                aq[i][0] += a * q0; aq[i][1] += a * q1; aq[i][2] += a * q2;
            }
        }
        __syncthreads();
    }

#pragma unroll
    for (int i = 0; i < 8; ++i) {
        int m = m0 + ty * 8 + i;
        if (m < NN) {
            float* pr = p + (size_t)m * 96;
            float* qr = q + (size_t)m * 96;
            pr[tx]      = ap[i][0]; pr[tx + 32] = ap[i][1]; pr[tx + 64] = ap[i][2];
            qr[tx]      = aq[i][0]; qr[tx + 32] = aq[i][1]; qr[tx + 64] = aq[i][2];
        }
    }
}

// ---------------------------------------------------------------------------
// Edge kernel: one warp per edge, lanes 0..23 own one float4 each.
//   a   = tanh.approx((p[dst] + q[src] + b_gate) / sqrt(192))  -> streamed out
//   msg = h[src] * a * d[dst]*d[src]
//   y[dst] += (dot(msg, Wc0), dot(msg, Wc1))   -- 8B atomic per edge
// ---------------------------------------------------------------------------
__global__ void edge_kernel(const int*   __restrict__ src,
                            const int*   __restrict__ dst,
                            const float* __restrict__ d,
                            const float* __restrict__ bgate,
                            const float* __restrict__ Wc,
                            float* __restrict__ a_out,
                            float* __restrict__ y)
{
    int e = blockIdx.x * 8 + (threadIdx.x >> 5);
    int lane = threadIdx.x & 31;

    int s = __ldg(src + e);
    int t = __ldg(dst + e);
    float ed = __ldg(d + t) * __ldg(d + s);

    float s0 = 0.f, s1 = 0.f;

    if (lane < 24) {
        const float4 pv = __ldg(((const float4*)(g_p + (size_t)t * H)) + lane);
        const float4 qv = __ldg(((const float4*)(g_q + (size_t)s * H)) + lane);
        const float4 hv = __ldg(((const float4*)(g_h + (size_t)s * H)) + lane);
        const float4 bv = __ldg(((const float4*)bgate) + lane);

        const float ic = 0.07216878364870322f;   // 1/sqrt(192)
        float4 av;
        av.x = tanh_fast((pv.x + qv.x + bv.x) * ic);
        av.y = tanh_fast((pv.y + qv.y + bv.y) * ic);
        av.z = tanh_fast((pv.z + qv.z + bv.z) * ic);
        av.w = tanh_fast((pv.w + qv.w + bv.w) * ic);

        // streaming store: don't let the 307MB 'a' output evict p/q/h from L2
        __stcs(((float4*)a_out) + (size_t)e * 24 + lane, av);

        float4 mv = make_float4(hv.x * av.x * ed, hv.y * av.y * ed,
                                hv.z * av.z * ed, hv.w * av.w * ed);

        const float4 w0 = __ldg(((const float4*)Wc) + lane);
        const float4 w1 = __ldg(((const float4*)(Wc + H)) + lane);

        s0 = mv.x * w0.x + mv.y * w0.y + mv.z * w0.z + mv.w * w0.w;
        s1 = mv.x * w1.x + mv.y * w1.y + mv.z * w1.z + mv.w * w1.w;
    }

#pragma unroll
    for (int o = 16; o; o >>= 1) {
        s0 += __shfl_xor_sync(0xffffffffu, s0, o);
        s1 += __shfl_xor_sync(0xffffffffu, s1, o);
    }

    if (lane == 0) {
        float* yp = y + (size_t)t * 2;
        asm volatile("red.global.add.v2.f32 [%0], {%1, %2};"
                     :: "l"(yp), "f"(s0), "f"(s1) : "memory");
    }
}

// ---------------------------------------------------------------------------
// log_softmax over the 2-class logits.
// ---------------------------------------------------------------------------
__global__ void clf_kernel(const float* __restrict__ y,
                           const float* __restrict__ bc,
                           float* __restrict__ out)
{
    int n = blockIdx.x * blockDim.x + threadIdx.x;
    if (n >= NN) return;
    float y0 = y[2 * n]     + bc[0];
    float y1 = y[2 * n + 1] + bc[1];
    float m  = fmaxf(y0, y1);
    float lse = m + logf(expf(y0 - m) + expf(y1 - m));
    out[2 * n]     = y0 - lse;
    out[2 * n + 1] = y1 - lse;
}

// ---------------------------------------------------------------------------
extern "C" void kernel_launch(void* const* d_in, const int* in_sizes, int n_in,
                              void* d_out, int out_size)
{
    const float* x      = (const float*)d_in[0];
    const float* d      = (const float*)d_in[1];
    const int*   src    = (const int*)  d_in[2];
    const int*   dst    = (const int*)  d_in[3];
    const float* W_in   = (const float*)d_in[4];
    const float* b_in   = (const float*)d_in[5];
    const float* W_gate = (const float*)d_in[6];
    const float* b_gate = (const float*)d_in[7];
    const float* W_clf  = (const float*)d_in[8];
    const float* b_clf  = (const float*)d_in[9];
    float* out = (float*)d_out;

    float *hp, *pp, *qp, *yp;
    cudaGetSymbolAddress((void**)&hp, g_h);
    cudaGetSymbolAddress((void**)&pp, g_p);
    cudaGetSymbolAddress((void**)&qp, g_q);
    cudaGetSymbolAddress((void**)&yp, g_y);

    zero_y_kernel<<<(NN * 2 + 255) / 256, 256>>>(yp);

    // h = x @ W_in^T + b_in
    gemm96<<<(NN + 63) / 64, 256>>>(x, W_in, b_in, hp, NN, IND);
    // p,q = h @ Wg halves (fused)
    gemm_pq<<<(NN + 63) / 64, 256>>>(hp, W_gate, pp, qp);

    // a + logits scatter (output tuple order: z [50000,2] first, then a)
    edge_kernel<<<NE / 8, 256>>>(src, dst, d, b_gate, W_clf, out + 2 * NN, yp);

    clf_kernel<<<(NN + 255) / 256, 256>>>(yp, b_clf, out);
}

// round 3
// speedup vs baseline: 1.5693x; 1.5693x over previous
#include <cuda_runtime.h>
#include <math.h>

#define NN  50000
#define NE  800000
#define H   96
#define IND 256
#define EPW 32   // edges per warp in edge_kernel

// Scratch (__device__ globals per allocation rules)
__device__ float g_h[(size_t)NN * H];
__device__ float g_p[(size_t)NN * H];
__device__ float g_q[(size_t)NN * H];
__device__ float g_y[(size_t)NN * 2];

__device__ __forceinline__ float tanh_fast(float x) {
    float r;
    asm("tanh.approx.f32 %0, %1;" : "=f"(r) : "f"(x));
    return r;
}

// ---------------------------------------------------------------------------
__global__ void zero_y_kernel(float* __restrict__ y) {
    int i = blockIdx.x * blockDim.x + threadIdx.x;
    if (i < NN * 2) y[i] = 0.f;
}

// ---------------------------------------------------------------------------
// C[m, 0..95] = sum_k A[m,k] * W[n*ldw + koff + k] (+ bias[n])
// BM=64, BN=96, BK=16, 256 threads.
// ---------------------------------------------------------------------------
__global__ void __launch_bounds__(256, 5)
gemm96(const float* __restrict__ A,
       const float* __restrict__ W,
       const float* __restrict__ bias,
       float* __restrict__ C,
       int M, int K, int ldw, int koff)
{
    __shared__ float As[16][68];
    __shared__ float Bs[16][96];

    const int tid = threadIdx.x;
    const int tx  = tid & 31;
    const int ty  = tid >> 5;
    const int m0  = blockIdx.x * 64;

    float acc[8][3];
#pragma unroll
    for (int i = 0; i < 8; ++i)
#pragma unroll
        for (int j = 0; j < 3; ++j) acc[i][j] = 0.f;

    for (int k0 = 0; k0 < K; k0 += 16) {
        {
            int row  = tid >> 2;
            int kseg = (tid & 3) << 2;
            float4 v = make_float4(0.f, 0.f, 0.f, 0.f);
            int gm = m0 + row;
            if (gm < M)
                v = *(const float4*)(A + (size_t)gm * K + k0 + kseg);
            As[kseg + 0][row] = v.x;
            As[kseg + 1][row] = v.y;
            As[kseg + 2][row] = v.z;
            As[kseg + 3][row] = v.w;
        }
        for (int i = tid; i < 96 * 16; i += 256) {
            int n = i >> 4, k = i & 15;
            Bs[k][n] = W[(size_t)n * ldw + koff + k0 + k];
        }
        __syncthreads();

#pragma unroll
        for (int k = 0; k < 16; ++k) {
            float b0 = Bs[k][tx], b1 = Bs[k][tx + 32], b2 = Bs[k][tx + 64];
#pragma unroll
            for (int i = 0; i < 8; ++i) {
                float a = As[k][ty * 8 + i];
                acc[i][0] += a * b0;
                acc[i][1] += a * b1;
                acc[i][2] += a * b2;
            }
        }
        __syncthreads();
    }

    float bb0 = bias ? bias[tx]      : 0.f;
    float bb1 = bias ? bias[tx + 32] : 0.f;
    float bb2 = bias ? bias[tx + 64] : 0.f;

#pragma unroll
    for (int i = 0; i < 8; ++i) {
        int m = m0 + ty * 8 + i;
        if (m < M) {
            float* cr = C + (size_t)m * 96;
            cr[tx]      = acc[i][0] + bb0;
            cr[tx + 32] = acc[i][1] + bb1;
            cr[tx + 64] = acc[i][2] + bb2;
        }
    }
}

// ---------------------------------------------------------------------------
// Edge kernel, batched: each warp owns 32 consecutive edges.
//  - src/dst indices vector-loaded once per warp (lane i holds edge i's pair)
//  - b_gate, Wc rows held in registers for the whole batch
//  - a = tanh.approx((p[dst]+q[src]+b_gate)/sqrt(192)) streamed to a_out
//  - y[dst] += d[dst]*d[src] * (dot(h[src]*a, Wc0), dot(..., Wc1))  (8B red)
// ---------------------------------------------------------------------------
__global__ void __launch_bounds__(256)
edge_kernel(const int*   __restrict__ src,
            const int*   __restrict__ dst,
            const float* __restrict__ d,
            const float* __restrict__ bgate,
            const float* __restrict__ Wc,
            float* __restrict__ a_out,
            float* __restrict__ y)
{
    const int warp = blockIdx.x * 8 + (threadIdx.x >> 5);
    const int lane = threadIdx.x & 31;
    const int e0   = warp * EPW;
    if (e0 >= NE) return;

    // batch-load this warp's 32 (src,dst) pairs: lane i -> edge e0+i
    const int bs = __ldg(src + e0 + lane);
    const int bt = __ldg(dst + e0 + lane);

    // per-lane invariants (lanes 0..23 carry 4 columns each)
    float4 bv = make_float4(0.f, 0.f, 0.f, 0.f);
    float4 w0 = bv, w1 = bv;
    if (lane < 24) {
        bv = __ldg(((const float4*)bgate) + lane);
        w0 = __ldg(((const float4*)Wc) + lane);
        w1 = __ldg(((const float4*)(Wc + H)) + lane);
    }
    const float ic = 0.07216878364870322f;   // 1/sqrt(192)

#pragma unroll 2
    for (int i = 0; i < EPW; ++i) {
        const int s = __shfl_sync(0xffffffffu, bs, i);
        const int t = __shfl_sync(0xffffffffu, bt, i);

        float s0 = 0.f, s1 = 0.f;
        if (lane < 24) {
            const float4 pv = __ldg(((const float4*)(g_p + (size_t)t * H)) + lane);
            const float4 qv = __ldg(((const float4*)(g_q + (size_t)s * H)) + lane);
            const float4 hv = __ldg(((const float4*)(g_h + (size_t)s * H)) + lane);

            float4 av;
            av.x = tanh_fast((pv.x + qv.x + bv.x) * ic);
            av.y = tanh_fast((pv.y + qv.y + bv.y) * ic);
            av.z = tanh_fast((pv.z + qv.z + bv.z) * ic);
            av.w = tanh_fast((pv.w + qv.w + bv.w) * ic);

            __stcs(((float4*)a_out) + (size_t)(e0 + i) * 24 + lane, av);

            const float4 mv = make_float4(hv.x * av.x, hv.y * av.y,
                                          hv.z * av.z, hv.w * av.w);
            s0 = mv.x * w0.x + mv.y * w0.y + mv.z * w0.z + mv.w * w0.w;
            s1 = mv.x * w1.x + mv.y * w1.y + mv.z * w1.z + mv.w * w1.w;
        }

#pragma unroll
        for (int o = 16; o; o >>= 1) {
            s0 += __shfl_xor_sync(0xffffffffu, s0, o);
            s1 += __shfl_xor_sync(0xffffffffu, s1, o);
        }

        if (lane == 0) {
            const float ed = __ldg(d + t) * __ldg(d + s);
            float* yp = y + (size_t)t * 2;
            asm volatile("red.global.add.v2.f32 [%0], {%1, %2};"
                         :: "l"(yp), "f"(ed * s0), "f"(ed * s1) : "memory");
        }
    }
}

// ---------------------------------------------------------------------------
__global__ void clf_kernel(const float* __restrict__ y,
                           const float* __restrict__ bc,
                           float* __restrict__ out)
{
    int n = blockIdx.x * blockDim.x + threadIdx.x;
    if (n >= NN) return;
    float y0 = y[2 * n]     + bc[0];
    float y1 = y[2 * n + 1] + bc[1];
    float m  = fmaxf(y0, y1);
    float lse = m + logf(expf(y0 - m) + expf(y1 - m));
    out[2 * n]     = y0 - lse;
    out[2 * n + 1] = y1 - lse;
}

// ---------------------------------------------------------------------------
extern "C" void kernel_launch(void* const* d_in, const int* in_sizes, int n_in,
                              void* d_out, int out_size)
{
    const float* x      = (const float*)d_in[0];
    const float* d      = (const float*)d_in[1];
    const int*   src    = (const int*)  d_in[2];
    const int*   dst    = (const int*)  d_in[3];
    const float* W_in   = (const float*)d_in[4];
    const float* b_in   = (const float*)d_in[5];
    const float* W_gate = (const float*)d_in[6];
    const float* b_gate = (const float*)d_in[7];
    const float* W_clf  = (const float*)d_in[8];
    const float* b_clf  = (const float*)d_in[9];
    float* out = (float*)d_out;

    float *hp, *pp, *qp, *yp;
    cudaGetSymbolAddress((void**)&hp, g_h);
    cudaGetSymbolAddress((void**)&pp, g_p);
    cudaGetSymbolAddress((void**)&qp, g_q);
    cudaGetSymbolAddress((void**)&yp, g_y);

    zero_y_kernel<<<(NN * 2 + 255) / 256, 256>>>(yp);

    // h = x @ W_in^T + b_in
    gemm96<<<(NN + 63) / 64, 256>>>(x, W_in, b_in, hp, NN, IND, IND, 0);
    // p = h @ Wg[:, :96]^T ; q = h @ Wg[:, 96:]^T   (separate: no spills)
    gemm96<<<(NN + 63) / 64, 256>>>(hp, W_gate, nullptr, pp, NN, H, 2 * H, 0);
    gemm96<<<(NN + 63) / 64, 256>>>(hp, W_gate, nullptr, qp, NN, H, 2 * H, H);

    // a + logits scatter (output tuple order: z [50000,2] first, then a)
    edge_kernel<<<NE / (EPW * 8), 256>>>(src, dst, d, b_gate, W_clf,
                                         out + 2 * NN, yp);

    clf_kernel<<<(NN + 255) / 256, 256>>>(yp, b_clf, out);
}